// round 6
// baseline (speedup 1.0000x reference)
#include <cuda_runtime.h>
#include <cstdint>

#define NN 2048
#define NBLK 148
#define NTHR 1024
#define EPSC 1e-10f
#define ITERS 50
#define FSTR 8  // flag stride in uints (32B) to spread L2 lines

// ---------------- device scratch (static, per harness rules) ---------------
__device__ float g_W[(size_t)NN * NN];   // W[i][j]  = exp(-|s_i - a_j|)
__device__ float g_WT[(size_t)NN * NN];  // WT[i][j] = exp(-|s_j - a_i|)
__device__ float g_lab[NN], g_s[NN];
__device__ float g_E[NN], g_Einv[NN], g_F[NN], g_Finv[NN];
__device__ float g_disc[NN];
__device__ float g_part0[NN];            // idcg partials
__device__ float g_u[NN], g_v[NN], g_part[NN];
__device__ float g_idcg;
__device__ unsigned g_flag[NBLK * FSTR];  // zero-init; monotonic per-CTA phase

// ---------------- scoped ops (no CCTL.IVALL — preserve L1D) ----------------
__device__ __forceinline__ unsigned ld_acq(const unsigned* p) {
    unsigned v;
    asm volatile("ld.acquire.gpu.u32 %0, [%1];" : "=r"(v) : "l"(p) : "memory");
    return v;
}
__device__ __forceinline__ void st_rel(unsigned* p, unsigned v) {
    asm volatile("st.release.gpu.u32 [%0], %1;" :: "l"(p), "r"(v) : "memory");
}
__device__ __forceinline__ void st_rlx_f(float* p, float v) {
    asm volatile("st.relaxed.gpu.f32 [%0], %1;" :: "l"(p), "f"(v) : "memory");
}

// warp 31: poll all CTA flags >= target (5 flags per lane, wrap-safe compare)
__device__ __forceinline__ void poll_flags(unsigned target, int lane) {
    bool ok;
    do {
        ok = true;
        #pragma unroll
        for (int i = 0; i < 5; i++) {
            int idx = lane + 32 * i;
            if (idx < NBLK)
                ok &= ((int)(ld_acq(&g_flag[idx * FSTR]) - target) >= 0);
        }
    } while (!__all_sync(0xffffffffu, ok));
}

__device__ __forceinline__ float warp_sum(float v) {
    #pragma unroll
    for (int o = 16; o; o >>= 1) v += __shfl_xor_sync(0xffffffffu, v, o);
    return v;
}

// half-row (1024 floats) dot with smem vector; 8 float4 per lane.
template <bool STREAM>
__device__ __forceinline__ float dot_half(const float* __restrict__ row,
                                          const float* __restrict__ sv, int lane) {
    const float4* r4 = reinterpret_cast<const float4*>(row);
    const float4* s4 = reinterpret_cast<const float4*>(sv);
    float a0 = 0.f, a1 = 0.f, a2 = 0.f, a3 = 0.f;
    #pragma unroll
    for (int k = 0; k < 8; k++) {
        float4 w = STREAM ? __ldcg(r4 + lane + 32 * k) : r4[lane + 32 * k];
        float4 v = s4[lane + 32 * k];
        a0 = fmaf(w.x, v.x, a0);
        a1 = fmaf(w.y, v.y, a1);
        a2 = fmaf(w.z, v.z, a2);
        a3 = fmaf(w.w, v.w, a3);
    }
    return warp_sum((a0 + a1) + (a2 + a3));
}

__global__ void __launch_bounds__(NTHR, 1)
softndcg_kernel(const float* __restrict__ y_pred,
                const float* __restrict__ y_true,
                float* __restrict__ out) {
    __shared__ __align__(16) float spool[NN];  // staging / reduce / build scratch
    __shared__ float s_part[32];
    __shared__ float s_u[14], s_v[14];
    __shared__ unsigned sbase;

    const int tid  = threadIdx.x;
    const int lane = tid & 31;
    const int warp = tid >> 5;
    const int bid  = blockIdx.x;
    const int gtid = bid * NTHR + tid;
    unsigned* myflag = &g_flag[bid * FSTR];

    if (tid == 0) sbase = ld_acq(myflag);  // replay-safe phase base
    __syncthreads();
    unsigned tg = sbase;

    // helper macros for phase sync
    #define CTA_DONE()  do { __syncthreads(); if (tid == 0) st_rel(myflag, tg); } while (0)
    #define WAIT_ALL()  do { if (warp == 31) poll_flags(tg, lane); __syncthreads(); } while (0)

    // ---- Phase A: elementwise precompute -----------------------------------
    if (gtid < NN) {
        float a = y_pred[gtid];
        float e = expf(a);
        g_E[gtid]    = e;
        g_Einv[gtid] = 1.0f / e;
        g_lab[gtid]  = exp2f(y_true[gtid]) - 1.0f;
        g_disc[gtid] = log2f((float)gtid + 2.0f);
    }
    tg++; CTA_DONE(); WAIT_ALL();

    // ---- Phase B: ranks (descending, stable) -------------------------------
    {
        int r = bid + NBLK * warp;  // warps 0..13 carry rows
        if (r < NN) {
            float ai = y_pred[r];
            float li = __ldcg(&g_lab[r]);
            int ca = 0, cl = 0;
            for (int j = lane; j < NN; j += 32) {
                float aj = y_pred[j];
                ca += (aj > ai) || (aj == ai && j < r);
                float lj = __ldcg(&g_lab[j]);
                cl += (lj > li) || (lj == li && j < r);
            }
            #pragma unroll
            for (int o = 16; o; o >>= 1) {
                ca += __shfl_xor_sync(0xffffffffu, ca, o);
                cl += __shfl_xor_sync(0xffffffffu, cl, o);
            }
            if (lane == 0) {
                g_s[ca]     = ai;                            // sorted scores
                g_part0[r]  = li / __ldcg(&g_disc[cl]);      // idcg contribution
            }
        }
    }
    tg++; CTA_DONE(); WAIT_ALL();

    // ---- Phase C: F = exp(s); CTA0 reduces idcg ----------------------------
    if (gtid < NN) {
        float f = expf(__ldcg(&g_s[gtid]));
        g_F[gtid]    = f;
        g_Finv[gtid] = 1.0f / f;
    }
    if (bid == 0) {
        spool[tid] = __ldcg(&g_part0[tid]) + __ldcg(&g_part0[tid + NTHR]);
        __syncthreads();
        #pragma unroll
        for (int s2 = NTHR / 2; s2 > 0; s2 >>= 1) {
            if (tid < s2) spool[tid] += spool[tid + s2];
            __syncthreads();
        }
        if (tid == 0) g_idcg = spool[0];
    }
    tg++; CTA_DONE(); WAIT_ALL();

    // ---- Phase D: build W + WT directly, fused rowsum -> u0 ----------------
    {
        // thread owns column pair (2*tid, 2*tid+1), resident across 14 rows
        const float2* E2p  = reinterpret_cast<const float2*>(g_E);
        const float2* Ei2p = reinterpret_cast<const float2*>(g_Einv);
        const float2* F2p  = reinterpret_cast<const float2*>(g_F);
        const float2* Fi2p = reinterpret_cast<const float2*>(g_Finv);
        float2 E2  = __ldcg(E2p  + tid);
        float2 Ei2 = __ldcg(Ei2p + tid);
        float2 F2  = __ldcg(F2p  + tid);
        float2 Fi2 = __ldcg(Fi2p + tid);

        float acc[14];
        #pragma unroll
        for (int k = 0; k < 14; k++) {
            acc[k] = 0.f;
            int r = bid + NBLK * k;
            if (r < NN) {
                float fr  = __ldcg(&g_F[r]);
                float fir = __ldcg(&g_Finv[r]);
                float er  = __ldcg(&g_E[r]);
                float eir = __ldcg(&g_Einv[r]);
                float2 w, wt;
                w.x  = fminf(E2.x * fir, fr * Ei2.x);
                w.y  = fminf(E2.y * fir, fr * Ei2.y);
                wt.x = fminf(er * Fi2.x, F2.x * eir);
                wt.y = fminf(er * Fi2.y, F2.y * eir);
                reinterpret_cast<float2*>(g_W  + (size_t)r * NN)[tid] = w;
                reinterpret_cast<float2*>(g_WT + (size_t)r * NN)[tid] = wt;
                acc[k] = w.x + w.y;
            }
        }
        // rowsum reduce: warp partials -> smem (aliased on spool) -> one warp/row
        float* s_red = spool;  // [32 warps][14 rows]
        #pragma unroll
        for (int k = 0; k < 14; k++) {
            float ws = warp_sum(acc[k]);
            if (lane == 0) s_red[warp * 14 + k] = ws;
        }
        if (tid < 14) s_v[tid] = 1.0f;  // Sinkhorn v init
        __syncthreads();
        if (warp < 14) {
            int r = bid + NBLK * warp;
            if (r < NN) {
                float s = warp_sum(s_red[lane * 14 + warp]);
                if (lane == 0) st_rlx_f(&g_u[r], 1.0f / s);
            }
        }
    }
    tg++; CTA_DONE();  // u0 published

    const int k13  = warp >> 1;          // row slot 0..13 (warps 0..27)
    const int half = warp & 1;
    const int myr  = bid + NBLK * k13;
    const bool rowok = (warp < 28) && (myr < NN);

    float ucur_known = 0.f;  // not used; s_u holds per-row u

    // ---- Sinkhorn: 50 iterations ------------------------------------------
    for (int t = 1; t <= ITERS; t++) {
        // ===== col step: v <- v / clip(v * (W^T u), EPS) =====
        WAIT_ALL();
        spool[tid]        = __ldcg(&g_u[tid]);
        spool[tid + NTHR] = __ldcg(&g_u[tid + NTHR]);
        __syncthreads();
        if (t == 1 && tid < 14) {
            int r = bid + NBLK * tid;
            if (r < NN) s_u[tid] = spool[r];
        }
        if (rowok) {
            const float* rp = g_WT + (size_t)myr * NN + half * 1024;
            const float* sp = spool + half * 1024;
            float a = (k13 < 13) ? dot_half<false>(rp, sp, lane)
                                 : dot_half<true >(rp, sp, lane);
            if (lane == 0) s_part[warp] = a;
        }
        __syncthreads();
        if (warp == 0) {
            if (lane < 14) {
                int r = bid + NBLK * lane;
                if (r < NN) {
                    float a  = s_part[2 * lane] + s_part[2 * lane + 1];
                    float vv = s_v[lane];
                    vv = vv / fmaxf(vv * a, EPSC);
                    s_v[lane] = vv;
                    st_rlx_f(&g_v[r], vv);
                }
            }
            __syncwarp();
            if (lane == 0) st_rel(myflag, tg + 1);
        }
        tg++;

        // ===== row step: u <- u / clip(u * (W v), EPS) =====
        WAIT_ALL();
        spool[tid]        = __ldcg(&g_v[tid]);
        spool[tid + NTHR] = __ldcg(&g_v[tid + NTHR]);
        __syncthreads();
        if (rowok) {
            const float* rp = g_W + (size_t)myr * NN + half * 1024;
            const float* sp = spool + half * 1024;
            float a = (k13 < 13) ? dot_half<false>(rp, sp, lane)
                                 : dot_half<true >(rp, sp, lane);
            if (lane == 0) s_part[warp] = a;
        }
        __syncthreads();
        if (warp == 0) {
            if (lane < 14) {
                int r = bid + NBLK * lane;
                if (r < NN) {
                    float a  = s_part[2 * lane] + s_part[2 * lane + 1];
                    float uu = s_u[lane];
                    uu = uu / fmaxf(uu * a, EPSC);
                    s_u[lane] = uu;
                    st_rlx_f(&g_u[r], uu);
                }
            }
            __syncwarp();
            if (lane == 0) st_rel(myflag, tg + 1);
        }
        tg++;
    }
    (void)ucur_known;

    // ---- Final: dcg_i = u_i * (W (v .* lab))_i / disc_i --------------------
    // spool still holds v_50 (staged in last row step); s_u holds u_50.
    spool[tid]        *= __ldcg(&g_lab[tid]);
    spool[tid + NTHR] *= __ldcg(&g_lab[tid + NTHR]);
    __syncthreads();
    if (rowok) {
        const float* rp = g_W + (size_t)myr * NN + half * 1024;
        const float* sp = spool + half * 1024;
        float a = (k13 < 13) ? dot_half<false>(rp, sp, lane)
                             : dot_half<true >(rp, sp, lane);
        if (lane == 0) s_part[warp] = a;
    }
    __syncthreads();
    if (warp == 0) {
        if (lane < 14) {
            int r = bid + NBLK * lane;
            if (r < NN) {
                float a = s_part[2 * lane] + s_part[2 * lane + 1];
                st_rlx_f(&g_part[r], s_u[lane] * a / __ldcg(&g_disc[r]));
            }
        }
        __syncwarp();
        if (lane == 0) st_rel(myflag, tg + 1);
    }
    tg++;

    // ---- CTA0 gathers partials, reduces, writes output ---------------------
    if (bid == 0) {
        WAIT_ALL();
        float v = __ldcg(&g_part[tid]) + __ldcg(&g_part[tid + NTHR]);
        spool[tid] = v;
        __syncthreads();
        #pragma unroll
        for (int s2 = NTHR / 2; s2 > 0; s2 >>= 1) {
            if (tid < s2) spool[tid] += spool[tid + s2];
            __syncthreads();
        }
        if (tid == 0) out[0] = 1.0f - spool[0] / g_idcg;
    }
    #undef CTA_DONE
    #undef WAIT_ALL
}

extern "C" void kernel_launch(void* const* d_in, const int* in_sizes, int n_in,
                              void* d_out, int out_size) {
    const float* y_pred = (const float*)d_in[0];
    const float* y_true = (const float*)d_in[1];
    float* out = (float*)d_out;
    (void)in_sizes; (void)n_in; (void)out_size;
    softndcg_kernel<<<NBLK, NTHR>>>(y_pred, y_true, out);
}

// round 7
// speedup vs baseline: 5.7751x; 5.7751x over previous
#include <cuda_runtime.h>

#define NN 2048
#define NBLK 148
#define NTHR 1024
#define EPSC 1e-10f
#define ITERS 50

// ---------------- device scratch (static, per harness rules) ---------------
__device__ float g_s[NN];      // scores sorted descending
__device__ float g_labs[NN];   // labels permuted by score-rank (sorted basis)
__device__ float g_part0[NN];  // idcg partials
__device__ unsigned g_arrive = 0;
__device__ unsigned g_gen = 0;

// ---------------- scoped ops (no CCTL.IVALL — preserve caches) -------------
__device__ __forceinline__ unsigned ld_acq(const unsigned* p) {
    unsigned v;
    asm volatile("ld.acquire.gpu.u32 %0, [%1];" : "=r"(v) : "l"(p) : "memory");
    return v;
}
__device__ __forceinline__ void st_rel(unsigned* p, unsigned v) {
    asm volatile("st.release.gpu.u32 [%0], %1;" :: "l"(p), "r"(v) : "memory");
}
__device__ __forceinline__ void st_rlx(unsigned* p, unsigned v) {
    asm volatile("st.relaxed.gpu.u32 [%0], %1;" :: "l"(p), "r"(v) : "memory");
}
__device__ __forceinline__ unsigned atom_add_rel(unsigned* p, unsigned v) {
    unsigned o;
    asm volatile("atom.add.release.gpu.u32 %0, [%1], %2;"
                 : "=r"(o) : "l"(p), "r"(v) : "memory");
    return o;
}

// Central grid barrier (R3-proven). Used exactly once.
__device__ __forceinline__ void grid_sync(unsigned& gen) {
    __syncthreads();
    if (threadIdx.x == 0) {
        gen++;
        unsigned prev = atom_add_rel(&g_arrive, 1u);
        if (prev == NBLK - 1) {
            st_rlx(&g_arrive, 0u);
            st_rel(&g_gen, gen);
        } else {
            while (ld_acq(&g_gen) != gen) { }
        }
    }
    __syncthreads();
}

__device__ __forceinline__ float warp_sum(float v) {
    #pragma unroll
    for (int o = 16; o; o >>= 1) v += __shfl_xor_sync(0xffffffffu, v, o);
    return v;
}

// inclusive warp scan of float2
__device__ __forceinline__ float2 wscan2(float2 v, int lane) {
    #pragma unroll
    for (int o = 1; o < 32; o <<= 1) {
        float ax = __shfl_up_sync(0xffffffffu, v.x, o);
        float ay = __shfl_up_sync(0xffffffffu, v.y, o);
        if (lane >= o) { v.x += ax; v.y += ay; }
    }
    return v;
}

struct O2 { float a, b; };

// out = W~ x  where W~[k][m] = exp(-|s_k - s_m|), s sorted descending.
// Thread owns k0=2*tid, k1=k0+1. xr0/xr1 = x at NN-1-k0 / NN-1-k1.
// (W~x)_k = F_k * A_k + Finv_k * (suffix_k - w_k),
//   A = inclusive prefix of x/F,  suffix_k = sum_{m>=k} x_m*F_m.
// Packed scan element E[k] = (z_k, w_{NN-1-k}) -> one float2 scan serves both.
__device__ __forceinline__ O2 applyW(
    float x0, float x1, float xr0, float xr1,
    float F0, float F1, float Fi0, float Fi1, float Fr0, float Fr1,
    float4* sS4, float2* swarp2, int tid, int lane, int warp)
{
    float z0 = x0 * Fi0, z1 = x1 * Fi1;
    float wr0 = xr0 * Fr0, wr1 = xr1 * Fr1;  // w at NN-1-k0, NN-1-k1
    float2 a = make_float2(z0, wr0);
    float2 b = make_float2(z1, wr1);
    float2 pr = make_float2(a.x + b.x, a.y + b.y);
    float2 wp = wscan2(pr, lane);
    if (lane == 31) swarp2[warp] = wp;
    __syncthreads();
    if (warp == 0) {
        float2 t = swarp2[lane];
        float2 ts = wscan2(t, lane);
        swarp2[lane] = make_float2(ts.x - t.x, ts.y - t.y);  // exclusive
    }
    __syncthreads();
    float2 base = swarp2[warp];
    float ex = base.x + (wp.x - pr.x);
    float ey = base.y + (wp.y - pr.y);
    float S0x = ex + z0,  S0y = ey + wr0;   // inclusive scan at k0
    float S1x = S0x + z1, S1y = S0y + wr1;  // inclusive scan at k1
    sS4[tid] = make_float4(S0x, S0y, S1x, S1y);
    __syncthreads();
    float4 Sr = sS4[NTHR - 1 - tid];
    // sS4[j] = (S[2j].x,S[2j].y,S[2j+1].x,S[2j+1].y), j=1023-tid:
    //   2j+1 = NN-1-k0 -> suffix_k0 = Sr.w ; 2j = NN-1-k1 -> suffix_k1 = Sr.y
    float suf0 = Sr.w, suf1 = Sr.y;
    float w0 = x0 * F0, w1 = x1 * F1;
    O2 o;
    o.a = fmaf(F0, S0x, Fi0 * (suf0 - w0));
    o.b = fmaf(F1, S1x, Fi1 * (suf1 - w1));
    return o;
}

__global__ void __launch_bounds__(NTHR, 1)
softndcg_kernel(const float* __restrict__ y_pred,
                const float* __restrict__ y_true,
                float* __restrict__ out)
{
    __shared__ float2 sU2[NN / 2];   // u in sorted basis (pairs)
    __shared__ float2 sV2[NN / 2];   // v in sorted basis (pairs)
    __shared__ float4 sS4[NN / 2];   // scan results
    __shared__ float2 swarp2[32];
    __shared__ float  sred[32];
    __shared__ float  s_idcg;

    const int tid  = threadIdx.x;
    const int lane = tid & 31;
    const int warp = tid >> 5;
    const int bid  = blockIdx.x;

    unsigned gen = (tid == 0) ? ld_acq(&g_gen) : 0u;  // replay-safe

    // ---- Setup (all 148 CTAs): ranks + sorted arrays + idcg partials -------
    {
        int r = bid + NBLK * warp;  // warps 0..13 carry rows
        if (r < NN) {
            float ai = __ldg(&y_pred[r]);
            float ti = __ldg(&y_true[r]);
            int ca = 0, cl = 0;
            for (int j = lane; j < NN; j += 32) {
                float aj = __ldg(&y_pred[j]);
                ca += (aj > ai) || (aj == ai && j < r);
                float tj = __ldg(&y_true[j]);  // exp2 monotone: rank on y_true
                cl += (tj > ti) || (tj == ti && j < r);
            }
            #pragma unroll
            for (int o = 16; o; o >>= 1) {
                ca += __shfl_xor_sync(0xffffffffu, ca, o);
                cl += __shfl_xor_sync(0xffffffffu, cl, o);
            }
            if (lane == 0) {
                float lab = exp2f(ti) - 1.0f;
                g_s[ca]    = ai;                             // sorted scores
                g_labs[ca] = lab;                            // score-sorted labels
                g_part0[r] = lab / log2f((float)cl + 2.0f);  // idcg term
            }
        }
    }
    grid_sync(gen);
    if (bid != 0) return;  // only CTA0 runs the O(N) Sinkhorn

    // ---- CTA0: cache per-thread constants ----------------------------------
    const int k0 = 2 * tid, k1 = k0 + 1;
    float s0  = __ldcg(&g_s[k0]),       s1  = __ldcg(&g_s[k1]);
    float sr0 = __ldcg(&g_s[NN-1-k0]),  sr1 = __ldcg(&g_s[NN-1-k1]);
    float F0  = expf(s0),  F1  = expf(s1);
    float Fi0 = 1.0f / F0, Fi1 = 1.0f / F1;
    float Fr0 = expf(sr0), Fr1 = expf(sr1);
    float L0  = __ldcg(&g_labs[k0]),      L1  = __ldcg(&g_labs[k1]);
    float Lr0 = __ldcg(&g_labs[NN-1-k0]), Lr1 = __ldcg(&g_labs[NN-1-k1]);

    // idcg reduction (overlapped with first bars)
    float p = __ldcg(&g_part0[k0]) + __ldcg(&g_part0[k1]);
    p = warp_sum(p);
    if (lane == 0) sred[warp] = p;
    __syncthreads();
    if (warp == 0) {
        float q = warp_sum(sred[lane]);
        if (lane == 0) s_idcg = q;
    }
    // (no extra bar: s_idcg consumed only at the very end, many bars later)

    // ---- u0 = 1 / rowsum(W~)  (x = 1), v0 = 1 ------------------------------
    float2 uu, vv = make_float2(1.0f, 1.0f);
    {
        O2 o = applyW(1.f, 1.f, 1.f, 1.f, F0, F1, Fi0, Fi1, Fr0, Fr1,
                      sS4, swarp2, tid, lane, warp);
        uu = make_float2(1.0f / o.a, 1.0f / o.b);
        sU2[tid] = uu;
        __syncthreads();
    }

    // ---- Sinkhorn: 50 iterations, all intra-CTA ----------------------------
    for (int t = 0; t < ITERS; t++) {
        // col step: v <- v / clip(v * (W~ u), EPS)
        {
            float2 xr = sU2[NTHR - 1 - tid];  // (u[NN-2-k0], u[NN-1-k0])
            O2 o = applyW(uu.x, uu.y, xr.y, xr.x, F0, F1, Fi0, Fi1, Fr0, Fr1,
                          sS4, swarp2, tid, lane, warp);
            vv.x = vv.x / fmaxf(vv.x * o.a, EPSC);
            vv.y = vv.y / fmaxf(vv.y * o.b, EPSC);
            sV2[tid] = vv;
            __syncthreads();
        }
        // row step: u <- u / clip(u * (W~ v), EPS)
        {
            float2 xr = sV2[NTHR - 1 - tid];
            O2 o = applyW(vv.x, vv.y, xr.y, xr.x, F0, F1, Fi0, Fi1, Fr0, Fr1,
                          sS4, swarp2, tid, lane, warp);
            uu.x = uu.x / fmaxf(uu.x * o.a, EPSC);
            uu.y = uu.y / fmaxf(uu.y * o.b, EPSC);
            sU2[tid] = uu;
            __syncthreads();
        }
    }

    // ---- Final: dcg = sum_k u_k * (W~ (v .* labs))_k / disc_k --------------
    {
        float y0 = vv.x * L0, y1 = vv.y * L1;
        float2 xr = sV2[NTHR - 1 - tid];
        float yr0 = xr.y * Lr0;  // (v.*labs) at NN-1-k0
        float yr1 = xr.x * Lr1;  // (v.*labs) at NN-1-k1
        O2 o = applyW(y0, y1, yr0, yr1, F0, F1, Fi0, Fi1, Fr0, Fr1,
                      sS4, swarp2, tid, lane, warp);
        float d = uu.x * o.a / log2f((float)k0 + 2.0f)
                + uu.y * o.b / log2f((float)k1 + 2.0f);
        d = warp_sum(d);
        if (lane == 0) sred[warp] = d;
        __syncthreads();
        if (warp == 0) {
            float q = warp_sum(sred[lane]);
            if (lane == 0) out[0] = 1.0f - q / s_idcg;
        }
    }
}

extern "C" void kernel_launch(void* const* d_in, const int* in_sizes, int n_in,
                              void* d_out, int out_size) {
    const float* y_pred = (const float*)d_in[0];
    const float* y_true = (const float*)d_in[1];
    float* out = (float*)d_out;
    (void)in_sizes; (void)n_in; (void)out_size;
    softndcg_kernel<<<NBLK, NTHR>>>(y_pred, y_true, out);
}